// round 12
// baseline (speedup 1.0000x reference)
#include <cuda_runtime.h>
#include <stdint.h>
#include <stddef.h>

#define N_NODES 100000
#define N_EDGES 600000
#define NODE_IN 387
#define AGGR_LD 388          // padded stride: 388*4 = 1552 B, 16B-aligned rows
#define HID 128
#define EDGE_DIM 7

// ---------------- device scratch (allocation-free) ----------------
__device__ float g_aggr1[(size_t)N_NODES * AGGR_LD];   // 155 MB (reused as gA/gB later)
__device__ float g_xpad [(size_t)N_NODES * AGGR_LD];   // 155 MB padded copy of x
__device__ float g_h1   [(size_t)N_NODES * HID];
__device__ float g_aggr2[(size_t)N_NODES * HID];
__device__ float g_h2   [(size_t)N_NODES * HID];
__device__ int   g_src[N_EDGES];
__device__ int   g_dst[N_EDGES];

// ---------------- packed fp32x2 + vector RED helpers ----------------
__device__ __forceinline__ void red4(float* addr, float4 v) {
    asm volatile("red.global.add.v4.f32 [%0], {%1,%2,%3,%4};"
                 :: "l"(addr), "f"(v.x), "f"(v.y), "f"(v.z), "f"(v.w) : "memory");
}
__device__ __forceinline__ unsigned long long pk2(float x, float y) {
    unsigned long long r;
    asm("mov.b64 %0, {%1,%2};" : "=l"(r) : "f"(x), "f"(y));
    return r;
}
__device__ __forceinline__ void upk2(unsigned long long v, float& x, float& y) {
    asm("mov.b64 {%0,%1}, %2;" : "=f"(x), "=f"(y) : "l"(v));
}
__device__ __forceinline__ unsigned long long ffma2(
    unsigned long long a, unsigned long long b, unsigned long long c) {
    unsigned long long d;
    asm("fma.rn.f32x2 %0, %1, %2, %3;" : "=l"(d) : "l"(a), "l"(b), "l"(c));
    return d;
}
__device__ __forceinline__ unsigned long long fadd2(
    unsigned long long a, unsigned long long b) {
    unsigned long long d;
    asm("add.rn.f32x2 %0, %1, %2;" : "=l"(d) : "l"(a), "l"(b));
    return d;
}

// ---------------- index canonicalization (per-block dtype detection) ----------------
__global__ void convert_idx(const void* ei) {
    __shared__ int s_is64;
    if (threadIdx.x == 0) {
        const long long* p = (const long long*)ei;
        int ok = 1;
        #pragma unroll 4
        for (int i = 0; i < 256; i++) {
            long long v = p[i];
            if (v < 0 || v >= (long long)N_NODES) { ok = 0; break; }
        }
        s_is64 = ok;
    }
    __syncthreads();
    int is64 = s_is64;
    int stride = gridDim.x * blockDim.x;
    for (int i = blockIdx.x * blockDim.x + threadIdx.x; i < 2 * N_EDGES; i += stride) {
        int v;
        if (is64) v = (int)((const long long*)ei)[i];
        else      v = ((const int*)ei)[i];
        if (i < N_EDGES) g_src[i] = v;
        else             g_dst[i - N_EDGES] = v;
    }
}

// ---------------- init: seed aggr1 = x (padded) and x_pad = x (padded) ----------------
__global__ void init_pads(const float* __restrict__ x,
                          float* __restrict__ aggr, float* __restrict__ xpad) {
    int lane = threadIdx.x & 31;
    int w = (blockIdx.x * blockDim.x + threadIdx.x) >> 5;
    int nw = (gridDim.x * blockDim.x) >> 5;
    for (int n = w; n < N_NODES; n += nw) {
        const float* xr = x + (size_t)n * NODE_IN;
        float* ar = aggr + (size_t)n * AGGR_LD;
        float* pr = xpad + (size_t)n * AGGR_LD;
        #pragma unroll
        for (int i = 0; i < 12; i++) {
            float v = __ldg(&xr[lane + 32 * i]);
            ar[lane + 32 * i] = v;
            pr[lane + 32 * i] = v;
        }
        if (lane < 4) {
            float v = (lane < 3) ? __ldg(&xr[384 + lane]) : 0.f;
            ar[384 + lane] = v;
            pr[384 + lane] = v;
        }
    }
}

// ---------------- vectorized flat copy ----------------
__global__ void copy4(const float* __restrict__ src, float* __restrict__ dst, int n4) {
    int stride = gridDim.x * blockDim.x;
    const float4* s = (const float4*)src;
    float4* d = (float4*)dst;
    for (int i = blockIdx.x * blockDim.x + threadIdx.x; i < n4; i += stride)
        d[i] = s[i];
}

// ---------------- conv1 message+scatter: 128-chunk, LDG.128 + FFMA2 + RED.128 ----------
template<int DLO, bool REM>
__global__ __launch_bounds__(256) void edge_msg_pass(
    const float* __restrict__ xpad, const float* __restrict__ eattr,
    const float* __restrict__ wg, const float* __restrict__ bg,
    float* __restrict__ aggr)
{
    __shared__ __align__(16) float sw[EDGE_DIM * 128];
    __shared__ __align__(16) float sb[128];
    __shared__ float swr[EDGE_DIM * 3];
    __shared__ float sbr[3];
    for (int i = threadIdx.x; i < EDGE_DIM * 128; i += 256) {
        int c = i >> 7, j = i & 127;
        sw[i] = wg[c * NODE_IN + DLO + j];
    }
    if (threadIdx.x < 128) sb[threadIdx.x] = bg[DLO + threadIdx.x];
    if (REM) {
        if (threadIdx.x < EDGE_DIM * 3) {
            int c = threadIdx.x / 3, j = threadIdx.x % 3;
            swr[c * 3 + j] = wg[c * NODE_IN + 384 + j];
        }
        if (threadIdx.x < 3) sbr[threadIdx.x] = bg[384 + threadIdx.x];
    }
    __syncthreads();
    const float4* sw4 = (const float4*)sw;
    const float4* sb4 = (const float4*)sb;

    int lane = threadIdx.x & 31;
    int gw = (blockIdx.x * 256 + threadIdx.x) >> 5;
    int nw = (gridDim.x * 256) >> 5;

    // loop-invariant packed weights (lane owns features DLO+4*lane..+3)
    unsigned long long Wlo[7], Whi[7];
    #pragma unroll
    for (int c = 0; c < 7; c++) {
        float4 W = sw4[c * 32 + lane];
        Wlo[c] = pk2(W.x, W.y);
        Whi[c] = pk2(W.z, W.w);
    }
    float4 B = sb4[lane];
    unsigned long long Blo = pk2(B.x, B.y);
    unsigned long long Bhi = pk2(B.z, B.w);

    for (int p = gw; p < N_EDGES / 2; p += nw) {
        int e0 = 2 * p;
        int2 ss = *(const int2*)&g_src[e0];
        int2 dd = *(const int2*)&g_dst[e0];
        float av = (lane < 14) ? eattr[(size_t)e0 * EDGE_DIM + lane] : 0.f;
        float a0[7], a1[7];
        #pragma unroll
        for (int c = 0; c < 7; c++) {
            a0[c] = __shfl_sync(0xffffffffu, av, c);
            a1[c] = __shfl_sync(0xffffffffu, av, c + 7);
        }

        float4 v0 = __ldg((const float4*)(xpad + (size_t)ss.x * AGGR_LD + DLO) + lane);
        float4 v1 = __ldg((const float4*)(xpad + (size_t)ss.y * AGGR_LD + DLO) + lane);

        unsigned long long m0lo = fadd2(Blo, pk2(v0.x, v0.y));
        unsigned long long m0hi = fadd2(Bhi, pk2(v0.z, v0.w));
        unsigned long long m1lo = fadd2(Blo, pk2(v1.x, v1.y));
        unsigned long long m1hi = fadd2(Bhi, pk2(v1.z, v1.w));
        #pragma unroll
        for (int c = 0; c < 7; c++) {
            unsigned long long a0p = pk2(a0[c], a0[c]);
            unsigned long long a1p = pk2(a1[c], a1[c]);
            m0lo = ffma2(a0p, Wlo[c], m0lo);
            m0hi = ffma2(a0p, Whi[c], m0hi);
            m1lo = ffma2(a1p, Wlo[c], m1lo);
            m1hi = ffma2(a1p, Whi[c], m1hi);
        }
        float4 r0, r1;
        upk2(m0lo, r0.x, r0.y); upk2(m0hi, r0.z, r0.w);
        upk2(m1lo, r1.x, r1.y); upk2(m1hi, r1.z, r1.w);
        r0.x = fmaxf(r0.x, 0.f); r0.y = fmaxf(r0.y, 0.f);
        r0.z = fmaxf(r0.z, 0.f); r0.w = fmaxf(r0.w, 0.f);
        r1.x = fmaxf(r1.x, 0.f); r1.y = fmaxf(r1.y, 0.f);
        r1.z = fmaxf(r1.z, 0.f); r1.w = fmaxf(r1.w, 0.f);

        red4(aggr + (size_t)dd.x * AGGR_LD + DLO + 4 * lane, r0);
        red4(aggr + (size_t)dd.y * AGGR_LD + DLO + 4 * lane, r1);

        if (REM) {
            if (lane < 3) {
                int f = 384 + lane;
                float q0 = sbr[lane] + __ldg(&xpad[(size_t)ss.x * AGGR_LD + f]);
                float q1 = sbr[lane] + __ldg(&xpad[(size_t)ss.y * AGGR_LD + f]);
                #pragma unroll
                for (int c = 0; c < 7; c++) {
                    float wv = swr[c * 3 + lane];
                    q0 = fmaf(a0[c], wv, q0);
                    q1 = fmaf(a1[c], wv, q1);
                }
                atomicAdd(&aggr[(size_t)dd.x * AGGR_LD + f], fmaxf(q0, 0.f));
                atomicAdd(&aggr[(size_t)dd.y * AGGR_LD + f], fmaxf(q1, 0.f));
            }
        }
    }
}

// ---------------- conv2 message+scatter (D=128, LDG.128 + FFMA2 + RED.128) ----------
__global__ __launch_bounds__(256) void edge_msg128(
    const float* __restrict__ xin, const float* __restrict__ eattr,
    const float* __restrict__ wg, const float* __restrict__ bg,
    float* __restrict__ aggr)
{
    __shared__ __align__(16) float sw[EDGE_DIM * HID];
    __shared__ __align__(16) float sb[HID];
    for (int i = threadIdx.x; i < EDGE_DIM * HID; i += 256) sw[i] = wg[i];
    if (threadIdx.x < HID) sb[threadIdx.x] = bg[threadIdx.x];
    __syncthreads();
    const float4* sw4 = (const float4*)sw;
    const float4* sb4 = (const float4*)sb;

    int lane = threadIdx.x & 31;
    int gw = (blockIdx.x * 256 + threadIdx.x) >> 5;
    int nw = (gridDim.x * 256) >> 5;

    unsigned long long Wlo[7], Whi[7];
    #pragma unroll
    for (int c = 0; c < 7; c++) {
        float4 W = sw4[c * 32 + lane];
        Wlo[c] = pk2(W.x, W.y);
        Whi[c] = pk2(W.z, W.w);
    }
    float4 B = sb4[lane];
    unsigned long long Blo = pk2(B.x, B.y);
    unsigned long long Bhi = pk2(B.z, B.w);

    for (int p = gw; p < N_EDGES / 2; p += nw) {
        int e0 = 2 * p;
        int2 ss = *(const int2*)&g_src[e0];
        int2 dd = *(const int2*)&g_dst[e0];
        float av = (lane < 14) ? eattr[(size_t)e0 * EDGE_DIM + lane] : 0.f;
        float a0[7], a1[7];
        #pragma unroll
        for (int c = 0; c < 7; c++) {
            a0[c] = __shfl_sync(0xffffffffu, av, c);
            a1[c] = __shfl_sync(0xffffffffu, av, c + 7);
        }

        float4 v0 = __ldg((const float4*)(xin + (size_t)ss.x * HID) + lane);
        float4 v1 = __ldg((const float4*)(xin + (size_t)ss.y * HID) + lane);

        unsigned long long m0lo = fadd2(Blo, pk2(v0.x, v0.y));
        unsigned long long m0hi = fadd2(Bhi, pk2(v0.z, v0.w));
        unsigned long long m1lo = fadd2(Blo, pk2(v1.x, v1.y));
        unsigned long long m1hi = fadd2(Bhi, pk2(v1.z, v1.w));
        #pragma unroll
        for (int c = 0; c < 7; c++) {
            unsigned long long a0p = pk2(a0[c], a0[c]);
            unsigned long long a1p = pk2(a1[c], a1[c]);
            m0lo = ffma2(a0p, Wlo[c], m0lo);
            m0hi = ffma2(a0p, Whi[c], m0hi);
            m1lo = ffma2(a1p, Wlo[c], m1lo);
            m1hi = ffma2(a1p, Whi[c], m1hi);
        }
        float4 r0, r1;
        upk2(m0lo, r0.x, r0.y); upk2(m0hi, r0.z, r0.w);
        upk2(m1lo, r1.x, r1.y); upk2(m1hi, r1.z, r1.w);
        r0.x = fmaxf(r0.x, 0.f); r0.y = fmaxf(r0.y, 0.f);
        r0.z = fmaxf(r0.z, 0.f); r0.w = fmaxf(r0.w, 0.f);
        r1.x = fmaxf(r1.x, 0.f); r1.y = fmaxf(r1.y, 0.f);
        r1.z = fmaxf(r1.z, 0.f); r1.w = fmaxf(r1.w, 0.f);

        red4(aggr + (size_t)dd.x * HID + 4 * lane, r0);
        red4(aggr + (size_t)dd.y * HID + 4 * lane, r1);
    }
}

// ---------------- tf32 helpers ----------------
__device__ __forceinline__ uint32_t f2tf32(float f) {
    uint32_t u;
    asm("cvt.rna.tf32.f32 %0, %1;" : "=r"(u) : "f"(f));
    return u;
}

// ---------------- dual tf32 GEMM: gA = A@Wa, gB = A@Wb  (K=128 fixed) ----------------
__global__ __launch_bounds__(256) void gemm_tc2(
    const float* __restrict__ A, const float* __restrict__ W,
    float* __restrict__ C0, float* __restrict__ C1, int M)
{
    __shared__ uint32_t As[128][36];
    __shared__ uint32_t Bs[32][132];

    const float* Wb = W + (size_t)blockIdx.y * 128 * 128;
    float* C = blockIdx.y ? C1 : C0;

    int t = threadIdx.x;
    int lane = t & 31;
    int warp = t >> 5;
    int wm = warp & 3;
    int wn = warp >> 2;
    int row0 = blockIdx.x * 128;
    int g = lane >> 2;
    int tt = lane & 3;

    float c[2][8][4];
    #pragma unroll
    for (int mt = 0; mt < 2; mt++)
        #pragma unroll
        for (int nt = 0; nt < 8; nt++)
            #pragma unroll
            for (int i = 0; i < 4; i++) c[mt][nt][i] = 0.f;

    for (int k0 = 0; k0 < 128; k0 += 32) {
        #pragma unroll
        for (int i = 0; i < 4; i++) {
            int idx = t + i * 256;
            int r = idx >> 3;
            int kq = (idx & 7) * 4;
            int gr = row0 + r;
            float4 v = make_float4(0.f, 0.f, 0.f, 0.f);
            if (gr < M) v = *(const float4*)&A[(size_t)gr * 128 + k0 + kq];
            *(uint4*)&As[r][kq] = make_uint4(f2tf32(v.x), f2tf32(v.y), f2tf32(v.z), f2tf32(v.w));
        }
        #pragma unroll
        for (int i = 0; i < 4; i++) {
            int idx = t + i * 256;
            int kk = idx >> 5;
            int nq = (idx & 31) * 4;
            float4 v = *(const float4*)&Wb[(size_t)(k0 + kk) * 128 + nq];
            *(uint4*)&Bs[kk][nq] = make_uint4(f2tf32(v.x), f2tf32(v.y), f2tf32(v.z), f2tf32(v.w));
        }
        __syncthreads();
        #pragma unroll
        for (int k8 = 0; k8 < 4; k8++) {
            int kb = k8 * 8;
            uint32_t a[2][4], b[8][2];
            #pragma unroll
            for (int mt = 0; mt < 2; mt++) {
                int ar = wm * 32 + mt * 16 + g;
                a[mt][0] = As[ar][kb + tt];
                a[mt][1] = As[ar + 8][kb + tt];
                a[mt][2] = As[ar][kb + tt + 4];
                a[mt][3] = As[ar + 8][kb + tt + 4];
            }
            #pragma unroll
            for (int nt = 0; nt < 8; nt++) {
                int bn = wn * 64 + nt * 8 + g;
                b[nt][0] = Bs[kb + tt][bn];
                b[nt][1] = Bs[kb + tt + 4][bn];
            }
            #pragma unroll
            for (int mt = 0; mt < 2; mt++)
                #pragma unroll
                for (int nt = 0; nt < 8; nt++) {
                    asm volatile(
                        "mma.sync.aligned.m16n8k8.row.col.f32.tf32.tf32.f32 "
                        "{%0,%1,%2,%3}, {%4,%5,%6,%7}, {%8,%9}, {%0,%1,%2,%3};\n"
                        : "+f"(c[mt][nt][0]), "+f"(c[mt][nt][1]),
                          "+f"(c[mt][nt][2]), "+f"(c[mt][nt][3])
                        : "r"(a[mt][0]), "r"(a[mt][1]), "r"(a[mt][2]), "r"(a[mt][3]),
                          "r"(b[nt][0]), "r"(b[nt][1]));
                }
        }
        __syncthreads();
    }

    #pragma unroll
    for (int nt = 0; nt < 8; nt++) {
        int col = wn * 64 + nt * 8 + 2 * tt;
        #pragma unroll
        for (int mt = 0; mt < 2; mt++) {
            int r = row0 + wm * 32 + mt * 16 + g;
            if (r < M)
                *(float2*)&C[(size_t)r * 128 + col] = make_float2(c[mt][nt][0], c[mt][nt][1]);
            if (r + 8 < M)
                *(float2*)&C[(size_t)(r + 8) * 128 + col] = make_float2(c[mt][nt][2], c[mt][nt][3]);
        }
    }
}

// ---------------- fused 2-layer MLP: C = relu(relu(A@W1+b1)@W2+b2), N=128 ----------------
__global__ __launch_bounds__(256) void mlp2_tc(
    const float* __restrict__ A, const float* __restrict__ W1,
    const float* __restrict__ b1, const float* __restrict__ W2,
    const float* __restrict__ b2, float* __restrict__ C,
    int M, int K, int lda)
{
    extern __shared__ uint32_t smemu[];
    uint32_t (*As)[36]  = (uint32_t(*)[36])smemu;
    uint32_t (*Bs)[132] = (uint32_t(*)[132])(smemu + 128 * 36);
    uint32_t (*Mid)[132]= (uint32_t(*)[132])(smemu + 128 * 36 + 32 * 132);

    int t = threadIdx.x;
    int lane = t & 31;
    int warp = t >> 5;
    int wm = warp & 3;
    int wn = warp >> 2;
    int row0 = blockIdx.x * 128;
    int g = lane >> 2;
    int tt = lane & 3;

    float c[2][8][4];
    #pragma unroll
    for (int mt = 0; mt < 2; mt++)
        #pragma unroll
        for (int nt = 0; nt < 8; nt++)
            #pragma unroll
            for (int i = 0; i < 4; i++) c[mt][nt][i] = 0.f;

    for (int k0 = 0; k0 < K; k0 += 32) {
        #pragma unroll
        for (int i = 0; i < 4; i++) {
            int idx = t + i * 256;
            int r = idx >> 3;
            int kq = (idx & 7) * 4;
            int gr = row0 + r;
            int gk = k0 + kq;
            float4 v = make_float4(0.f, 0.f, 0.f, 0.f);
            if (gr < M) {
                if (gk + 3 < K) {
                    v = *(const float4*)&A[(size_t)gr * lda + gk];
                } else {
                    float tv[4] = {0.f, 0.f, 0.f, 0.f};
                    #pragma unroll
                    for (int j = 0; j < 4; j++)
                        if (gk + j < K) tv[j] = __ldg(&A[(size_t)gr * lda + gk + j]);
                    v = make_float4(tv[0], tv[1], tv[2], tv[3]);
                }
            }
            *(uint4*)&As[r][kq] = make_uint4(f2tf32(v.x), f2tf32(v.y), f2tf32(v.z), f2tf32(v.w));
        }
        #pragma unroll
        for (int i = 0; i < 4; i++) {
            int idx = t + i * 256;
            int kk = idx >> 5;
            int nq = (idx & 31) * 4;
            float4 v = make_float4(0.f, 0.f, 0.f, 0.f);
            if (k0 + kk < K) v = *(const float4*)&W1[(size_t)(k0 + kk) * 128 + nq];
            *(uint4*)&Bs[kk][nq] = make_uint4(f2tf32(v.x), f2tf32(v.y), f2tf32(v.z), f2tf32(v.w));
        }
        __syncthreads();
        #pragma unroll
        for (int k8 = 0; k8 < 4; k8++) {
            int kb = k8 * 8;
            uint32_t a[2][4], b[8][2];
            #pragma unroll
            for (int mt = 0; mt < 2; mt++) {
                int ar = wm * 32 + mt * 16 + g;
                a[mt][0] = As[ar][kb + tt];
                a[mt][1] = As[ar + 8][kb + tt];
                a[mt][2] = As[ar][kb + tt + 4];
                a[mt][3] = As[ar + 8][kb + tt + 4];
            }
            #pragma unroll
            for (int nt = 0; nt < 8; nt++) {
                int bn = wn * 64 + nt * 8 + g;
                b[nt][0] = Bs[kb + tt][bn];
                b[nt][1] = Bs[kb + tt + 4][bn];
            }
            #pragma unroll
            for (int mt = 0; mt < 2; mt++)
                #pragma unroll
                for (int nt = 0; nt < 8; nt++) {
                    asm volatile(
                        "mma.sync.aligned.m16n8k8.row.col.f32.tf32.tf32.f32 "
                        "{%0,%1,%2,%3}, {%4,%5,%6,%7}, {%8,%9}, {%0,%1,%2,%3};\n"
                        : "+f"(c[mt][nt][0]), "+f"(c[mt][nt][1]),
                          "+f"(c[mt][nt][2]), "+f"(c[mt][nt][3])
                        : "r"(a[mt][0]), "r"(a[mt][1]), "r"(a[mt][2]), "r"(a[mt][3]),
                          "r"(b[nt][0]), "r"(b[nt][1]));
                }
        }
        __syncthreads();
    }

    #pragma unroll
    for (int nt = 0; nt < 8; nt++) {
        int col = wn * 64 + nt * 8 + 2 * tt;
        float bb0 = __ldg(&b1[col]);
        float bb1 = __ldg(&b1[col + 1]);
        #pragma unroll
        for (int mt = 0; mt < 2; mt++) {
            int r = wm * 32 + mt * 16 + g;
            Mid[r][col]         = f2tf32(fmaxf(c[mt][nt][0] + bb0, 0.f));
            Mid[r][col + 1]     = f2tf32(fmaxf(c[mt][nt][1] + bb1, 0.f));
            Mid[r + 8][col]     = f2tf32(fmaxf(c[mt][nt][2] + bb0, 0.f));
            Mid[r + 8][col + 1] = f2tf32(fmaxf(c[mt][nt][3] + bb1, 0.f));
            c[mt][nt][0] = 0.f; c[mt][nt][1] = 0.f; c[mt][nt][2] = 0.f; c[mt][nt][3] = 0.f;
        }
    }
    __syncthreads();

    for (int k0 = 0; k0 < 128; k0 += 32) {
        #pragma unroll
        for (int i = 0; i < 4; i++) {
            int idx = t + i * 256;
            int kk = idx >> 5;
            int nq = (idx & 31) * 4;
            float4 v = *(const float4*)&W2[(size_t)(k0 + kk) * 128 + nq];
            *(uint4*)&Bs[kk][nq] = make_uint4(f2tf32(v.x), f2tf32(v.y), f2tf32(v.z), f2tf32(v.w));
        }
        __syncthreads();
        #pragma unroll
        for (int k8 = 0; k8 < 4; k8++) {
            int kb = k0 + k8 * 8;
            uint32_t a[2][4], b[8][2];
            #pragma unroll
            for (int mt = 0; mt < 2; mt++) {
                int ar = wm * 32 + mt * 16 + g;
                a[mt][0] = Mid[ar][kb + tt];
                a[mt][1] = Mid[ar + 8][kb + tt];
                a[mt][2] = Mid[ar][kb + tt + 4];
                a[mt][3] = Mid[ar + 8][kb + tt + 4];
            }
            #pragma unroll
            for (int nt = 0; nt < 8; nt++) {
                int bn = wn * 64 + nt * 8 + g;
                b[nt][0] = Bs[(k8 * 8) + tt][bn];
                b[nt][1] = Bs[(k8 * 8) + tt + 4][bn];
            }
            #pragma unroll
            for (int mt = 0; mt < 2; mt++)
                #pragma unroll
                for (int nt = 0; nt < 8; nt++) {
                    asm volatile(
                        "mma.sync.aligned.m16n8k8.row.col.f32.tf32.tf32.f32 "
                        "{%0,%1,%2,%3}, {%4,%5,%6,%7}, {%8,%9}, {%0,%1,%2,%3};\n"
                        : "+f"(c[mt][nt][0]), "+f"(c[mt][nt][1]),
                          "+f"(c[mt][nt][2]), "+f"(c[mt][nt][3])
                        : "r"(a[mt][0]), "r"(a[mt][1]), "r"(a[mt][2]), "r"(a[mt][3]),
                          "r"(b[nt][0]), "r"(b[nt][1]));
                }
        }
        __syncthreads();
    }

    #pragma unroll
    for (int nt = 0; nt < 8; nt++) {
        int col = wn * 64 + nt * 8 + 2 * tt;
        float bb0 = __ldg(&b2[col]);
        float bb1 = __ldg(&b2[col + 1]);
        #pragma unroll
        for (int mt = 0; mt < 2; mt++) {
            int r = row0 + wm * 32 + mt * 16 + g;
            float v0 = fmaxf(c[mt][nt][0] + bb0, 0.f);
            float v1 = fmaxf(c[mt][nt][1] + bb1, 0.f);
            float v2 = fmaxf(c[mt][nt][2] + bb0, 0.f);
            float v3 = fmaxf(c[mt][nt][3] + bb1, 0.f);
            if (r < M)     *(float2*)&C[(size_t)r * 128 + col]       = make_float2(v0, v1);
            if (r + 8 < M) *(float2*)&C[(size_t)(r + 8) * 128 + col] = make_float2(v2, v3);
        }
    }
}

// ---------------- decomposed edge MLP output stage ----------------
__global__ __launch_bounds__(512) void edge_out(
    const float* __restrict__ Arow, const float* __restrict__ Brow,
    const float* __restrict__ eattr,
    const float* __restrict__ w1g,
    const float* __restrict__ b1g,
    const float* __restrict__ w2g, const float* __restrict__ b2g,
    float* __restrict__ out)
{
    __shared__ __align__(16) float wc[EDGE_DIM * 128];
    __shared__ __align__(16) float b1s[128];
    __shared__ float w2s[256];
    __shared__ float b2s[2];

    int t = threadIdx.x;
    for (int i = t; i < EDGE_DIM * 128; i += 512) wc[i] = w1g[256 * 128 + i];
    if (t < 128) b1s[t] = b1g[t];
    if (t < 256) w2s[t] = w2g[t];
    if (t < 2)   b2s[t] = b2g[t];
    __syncthreads();

    int lane = t & 31;
    int w = t >> 5;
    int gw = blockIdx.x * 16 + w;
    int ngw = gridDim.x * 16;

    const float4* A4 = (const float4*)Arow;
    const float4* B4 = (const float4*)Brow;
    const float4* wc4 = (const float4*)wc;

    float4 bb = *(const float4*)&b1s[lane * 4];
    float w20 = w2s[(lane * 4 + 0) * 2 + 0], w21 = w2s[(lane * 4 + 0) * 2 + 1];
    float w22 = w2s[(lane * 4 + 1) * 2 + 0], w23 = w2s[(lane * 4 + 1) * 2 + 1];
    float w24 = w2s[(lane * 4 + 2) * 2 + 0], w25 = w2s[(lane * 4 + 2) * 2 + 1];
    float w26 = w2s[(lane * 4 + 3) * 2 + 0], w27 = w2s[(lane * 4 + 3) * 2 + 1];
    float bo0 = b2s[0], bo1 = b2s[1];

    for (int p = gw; p < N_EDGES / 2; p += ngw) {
        int e0 = 2 * p, e1 = e0 + 1;
        int2 ss = *(const int2*)&g_src[e0];
        int2 dd = *(const int2*)&g_dst[e0];
        float4 va0 = A4[(size_t)ss.x * 32 + lane];
        float4 vb0 = B4[(size_t)dd.x * 32 + lane];
        float4 va1 = A4[(size_t)ss.y * 32 + lane];
        float4 vb1 = B4[(size_t)dd.y * 32 + lane];

        float av = (lane < 14) ? eattr[(size_t)e0 * EDGE_DIM + lane] : 0.f;
        float a0[7], a1[7];
        #pragma unroll
        for (int c = 0; c < 7; c++) {
            a0[c] = __shfl_sync(0xffffffffu, av, c);
            a1[c] = __shfl_sync(0xffffffffu, av, c + 7);
        }

        float4 c0 = make_float4(0.f, 0.f, 0.f, 0.f);
        float4 c1 = make_float4(0.f, 0.f, 0.f, 0.f);
        #pragma unroll
        for (int k = 0; k < EDGE_DIM; k++) {
            float4 wv = wc4[k * 32 + lane];
            c0.x = fmaf(a0[k], wv.x, c0.x); c1.x = fmaf(a1[k], wv.x, c1.x);
            c0.y = fmaf(a0[k], wv.y, c0.y); c1.y = fmaf(a1[k], wv.y, c1.y);
            c0.z = fmaf(a0[k], wv.z, c0.z); c1.z = fmaf(a1[k], wv.z, c1.z);
            c0.w = fmaf(a0[k], wv.w, c0.w); c1.w = fmaf(a1[k], wv.w, c1.w);
        }

        float h00 = fmaxf(va0.x + vb0.x + c0.x + bb.x, 0.f);
        float h01 = fmaxf(va0.y + vb0.y + c0.y + bb.y, 0.f);
        float h02 = fmaxf(va0.z + vb0.z + c0.z + bb.z, 0.f);
        float h03 = fmaxf(va0.w + vb0.w + c0.w + bb.w, 0.f);
        float h10 = fmaxf(va1.x + vb1.x + c1.x + bb.x, 0.f);
        float h11 = fmaxf(va1.y + vb1.y + c1.y + bb.y, 0.f);
        float h12 = fmaxf(va1.z + vb1.z + c1.z + bb.z, 0.f);
        float h13 = fmaxf(va1.w + vb1.w + c1.w + bb.w, 0.f);

        float s0o = h00 * w20 + h01 * w22 + h02 * w24 + h03 * w26;
        float s1o = h00 * w21 + h01 * w23 + h02 * w25 + h03 * w27;
        float s2o = h10 * w20 + h11 * w22 + h12 * w24 + h13 * w26;
        float s3o = h10 * w21 + h11 * w23 + h12 * w25 + h13 * w27;

        #pragma unroll
        for (int off = 16; off; off >>= 1) {
            s0o += __shfl_down_sync(0xffffffffu, s0o, off);
            s1o += __shfl_down_sync(0xffffffffu, s1o, off);
            s2o += __shfl_down_sync(0xffffffffu, s2o, off);
            s3o += __shfl_down_sync(0xffffffffu, s3o, off);
        }
        if (lane == 0) {
            *(float2*)&out[(size_t)e0 * 2] = make_float2(s0o + bo0, s1o + bo1);
            *(float2*)&out[(size_t)e1 * 2] = make_float2(s2o + bo0, s3o + bo1);
        }
    }
}

// ---------------- launch ----------------
extern "C" void kernel_launch(void* const* d_in, const int* in_sizes, int n_in,
                              void* d_out, int out_size) {
    const float* x    = (const float*)d_in[0];
    const void*  ei   = d_in[1];
    const float* ea   = (const float*)d_in[2];
    const float* e1w  = (const float*)d_in[3];
    const float* e1b  = (const float*)d_in[4];
    const float* m1w1 = (const float*)d_in[5];
    const float* m1b1 = (const float*)d_in[6];
    const float* m1w2 = (const float*)d_in[7];
    const float* m1b2 = (const float*)d_in[8];
    const float* e2w  = (const float*)d_in[9];
    const float* e2b  = (const float*)d_in[10];
    const float* m2w1 = (const float*)d_in[11];
    const float* m2b1 = (const float*)d_in[12];
    const float* m2w2 = (const float*)d_in[13];
    const float* m2b2 = (const float*)d_in[14];
    const float* emw1 = (const float*)d_in[15];
    const float* emb1 = (const float*)d_in[16];
    const float* emw2 = (const float*)d_in[17];
    const float* emb2 = (const float*)d_in[18];
    float* out = (float*)d_out;

    float *aggr1, *xpad, *h1, *aggr2, *h2;
    cudaGetSymbolAddress((void**)&aggr1, g_aggr1);
    cudaGetSymbolAddress((void**)&xpad,  g_xpad);
    cudaGetSymbolAddress((void**)&h1,    g_h1);
    cudaGetSymbolAddress((void**)&aggr2, g_aggr2);
    cudaGetSymbolAddress((void**)&h2,    g_h2);
    float* gA = aggr1;                                  // reuse aggr1 after conv1
    float* gB = aggr1 + (size_t)N_NODES * HID;

    size_t mlp_smem = (size_t)(128 * 36 + 32 * 132 + 128 * 132) * 4;
    cudaFuncSetAttribute(mlp2_tc, cudaFuncAttributeMaxDynamicSharedMemorySize, (int)mlp_smem);

    int gemm_grid = (N_NODES + 127) / 128;

    convert_idx<<<1024, 256>>>(ei);

    // conv1: seed aggr1 + xpad, then 3 L2-blocked vectorized scatter passes
    init_pads<<<2048, 256>>>(x, aggr1, xpad);
    edge_msg_pass<0,   false><<<2048, 256>>>(xpad, ea, e1w, e1b, aggr1);
    edge_msg_pass<128, false><<<2048, 256>>>(xpad, ea, e1w, e1b, aggr1);
    edge_msg_pass<256, true ><<<2048, 256>>>(xpad, ea, e1w, e1b, aggr1);
    mlp2_tc<<<gemm_grid, 256, mlp_smem>>>(aggr1, m1w1, m1b1, m1w2, m1b2, h1,
                                          N_NODES, NODE_IN, AGGR_LD);

    // conv2
    copy4<<<2048, 256>>>(h1, aggr2, (N_NODES * HID) / 4);
    edge_msg128<<<2048, 256>>>(h1, ea, e2w, e2b, aggr2);
    mlp2_tc<<<gemm_grid, 256, mlp_smem>>>(aggr2, m2w1, m2b1, m2w2, m2b2, h2,
                                          N_NODES, HID, HID);

    // edge MLP (decomposed): gA = h2@Wa, gB = h2@Wb in one launch
    {
        dim3 grid(gemm_grid, 2);
        gemm_tc2<<<grid, 256>>>(h2, emw1, gA, gB, N_NODES);
    }
    edge_out<<<296, 512>>>(gA, gB, ea, emw1, emb1, emw2, emb2, out);
}

// round 13
// speedup vs baseline: 1.0234x; 1.0234x over previous
#include <cuda_runtime.h>
#include <stdint.h>
#include <stddef.h>

#define N_NODES 100000
#define N_EDGES 600000
#define NODE_IN 387
#define AGGR_LD 388          // padded aggr stride: rows 16B-aligned for mlp2 float4 loads
#define HID 128
#define EDGE_DIM 7
#define NP1 98               // ceil((N_NODES+1)/1024)

// ---------------- device scratch (allocation-free) ----------------
__device__ float g_aggr1[(size_t)N_NODES * AGGR_LD];   // 155 MB (reused as gA/gB later)
__device__ float g_h1   [(size_t)N_NODES * HID];
__device__ float g_aggr2[(size_t)N_NODES * HID];
__device__ float g_h2   [(size_t)N_NODES * HID];
__device__ int   g_src[N_EDGES];
__device__ int   g_dst[N_EDGES];
__device__ int   g_cnt[N_NODES + 1];
__device__ int   g_rp [N_NODES + 1];      // row_ptr (inclusive scan of cnt)
__device__ int   g_cursor[N_NODES];
__device__ int   g_part[NP1];
__device__ int   g_poff[NP1];
__device__ int2  g_csr[N_EDGES];          // (src, edge_id) sorted by dst

// ---------------- packed fp32x2 helpers ----------------
__device__ __forceinline__ unsigned long long pk2(float x, float y) {
    unsigned long long r;
    asm("mov.b64 %0, {%1,%2};" : "=l"(r) : "f"(x), "f"(y));
    return r;
}
__device__ __forceinline__ void upk2(unsigned long long v, float& x, float& y) {
    asm("mov.b64 {%0,%1}, %2;" : "=f"(x), "=f"(y) : "l"(v));
}
__device__ __forceinline__ unsigned long long ffma2(
    unsigned long long a, unsigned long long b, unsigned long long c) {
    unsigned long long d;
    asm("fma.rn.f32x2 %0, %1, %2, %3;" : "=l"(d) : "l"(a), "l"(b), "l"(c));
    return d;
}
__device__ __forceinline__ unsigned long long fadd2(
    unsigned long long a, unsigned long long b) {
    unsigned long long d;
    asm("add.rn.f32x2 %0, %1, %2;" : "=l"(d) : "l"(a), "l"(b));
    return d;
}

// ---------------- CSR build ----------------
__global__ void zero_cnt() {
    int i = blockIdx.x * blockDim.x + threadIdx.x;
    if (i <= N_NODES) g_cnt[i] = 0;
}

// canonicalize indices (per-block dtype detection) + dst histogram
__global__ void convert_hist(const void* ei) {
    __shared__ int s_is64;
    if (threadIdx.x == 0) {
        const long long* p = (const long long*)ei;
        int ok = 1;
        #pragma unroll 4
        for (int i = 0; i < 256; i++) {
            long long v = p[i];
            if (v < 0 || v >= (long long)N_NODES) { ok = 0; break; }
        }
        s_is64 = ok;
    }
    __syncthreads();
    int is64 = s_is64;
    int stride = gridDim.x * blockDim.x;
    for (int i = blockIdx.x * blockDim.x + threadIdx.x; i < 2 * N_EDGES; i += stride) {
        int v;
        if (is64) v = (int)((const long long*)ei)[i];
        else      v = ((const int*)ei)[i];
        if (i < N_EDGES) {
            g_src[i] = v;
        } else {
            g_dst[i - N_EDGES] = v;
            atomicAdd(&g_cnt[v + 1], 1);
        }
    }
}

__global__ void scan1() {
    __shared__ int s[1024];
    int b = blockIdx.x, t = threadIdx.x;
    int i = b * 1024 + t;
    int v = (i <= N_NODES) ? g_cnt[i] : 0;
    s[t] = v;
    __syncthreads();
    for (int off = 1; off < 1024; off <<= 1) {
        int u = (t >= off) ? s[t - off] : 0;
        __syncthreads();
        s[t] += u;
        __syncthreads();
    }
    if (i <= N_NODES) g_rp[i] = s[t];
    if (t == 1023) g_part[b] = s[1023];
}

__global__ void scan2() {
    __shared__ int s[128];
    int t = threadIdx.x;
    int v = (t < NP1) ? g_part[t] : 0;
    s[t] = v;
    __syncthreads();
    for (int off = 1; off < 128; off <<= 1) {
        int u = (t >= off) ? s[t - off] : 0;
        __syncthreads();
        s[t] += u;
        __syncthreads();
    }
    if (t < NP1) g_poff[t] = s[t] - v;   // exclusive prefix of partials
}

__global__ void scan3() {
    int b = blockIdx.x, t = threadIdx.x;
    int i = b * 1024 + t;
    if (i <= N_NODES) {
        int r = g_rp[i] + g_poff[b];
        g_rp[i] = r;
        if (i < N_NODES) g_cursor[i] = r;
    }
}

__global__ void fill_csr() {
    int stride = gridDim.x * blockDim.x;
    for (int e = blockIdx.x * blockDim.x + threadIdx.x; e < N_EDGES; e += stride) {
        int d = g_dst[e];
        int pos = atomicAdd(&g_cursor[d], 1);
        g_csr[pos] = make_int2(g_src[e], e);
    }
}

// ---------------- conv1: warp-per-dst gather-aggregate, 128-feature chunk ----------------
// acc = x[dst,chunk] + sum_e relu(x[src_e,chunk] + ea_e@W + b); ONE plain store per dst.
template<int DLO, bool REM>
__global__ __launch_bounds__(256) void conv1_pass(
    const float* __restrict__ x, const float* __restrict__ eattr,
    const float* __restrict__ wg, const float* __restrict__ bg,
    float* __restrict__ aggr)
{
    __shared__ float sw[EDGE_DIM * 128];
    __shared__ float sb[128];
    __shared__ float swr[EDGE_DIM * 3];
    __shared__ float sbr[3];
    for (int i = threadIdx.x; i < EDGE_DIM * 128; i += 256) {
        int c = i >> 7, j = i & 127;
        sw[i] = wg[c * NODE_IN + DLO + j];
    }
    if (threadIdx.x < 128) sb[threadIdx.x] = bg[DLO + threadIdx.x];
    if (REM) {
        if (threadIdx.x < EDGE_DIM * 3) {
            int c = threadIdx.x / 3, j = threadIdx.x % 3;
            swr[c * 3 + j] = wg[c * NODE_IN + 384 + j];
        }
        if (threadIdx.x < 3) sbr[threadIdx.x] = bg[384 + threadIdx.x];
    }
    __syncthreads();

    int lane = threadIdx.x & 31;
    // lane owns features DLO + {lane, lane+32, lane+64, lane+96}; packed (f,f+32),(f+64,f+96)
    unsigned long long Wp0[7], Wp1[7];
    #pragma unroll
    for (int c = 0; c < 7; c++) {
        Wp0[c] = pk2(sw[c * 128 + lane],      sw[c * 128 + lane + 32]);
        Wp1[c] = pk2(sw[c * 128 + lane + 64], sw[c * 128 + lane + 96]);
    }
    unsigned long long Bp0 = pk2(sb[lane], sb[lane + 32]);
    unsigned long long Bp1 = pk2(sb[lane + 64], sb[lane + 96]);
    float wr[7], br = 0.f;
    if (REM) {
        #pragma unroll
        for (int c = 0; c < 7; c++) wr[c] = (lane < 3) ? swr[c * 3 + lane] : 0.f;
        br = (lane < 3) ? sbr[lane] : 0.f;
    }

    int gwarp = (blockIdx.x * 256 + threadIdx.x) >> 5;
    int nwarp = (gridDim.x * 256) >> 5;

    for (int d = gwarp; d < N_NODES; d += nwarp) {
        int beg = g_rp[d];
        int end = g_rp[d + 1];
        const float* xd = x + (size_t)d * NODE_IN + DLO;
        float acc0 = __ldg(&xd[lane]);
        float acc1 = __ldg(&xd[lane + 32]);
        float acc2 = __ldg(&xd[lane + 64]);
        float acc3 = __ldg(&xd[lane + 96]);
        float accr = 0.f;
        if (REM && lane < 3) accr = __ldg(&x[(size_t)d * NODE_IN + 384 + lane]);

        int i = beg;
        for (; i + 1 < end; i += 2) {
            int2 se0 = g_csr[i];
            int2 se1 = g_csr[i + 1];
            float av0 = (lane < 7) ? __ldg(&eattr[(size_t)se0.y * EDGE_DIM + lane]) : 0.f;
            float av1 = (lane < 7) ? __ldg(&eattr[(size_t)se1.y * EDGE_DIM + lane]) : 0.f;
            const float* xs0 = x + (size_t)se0.x * NODE_IN + DLO;
            const float* xs1 = x + (size_t)se1.x * NODE_IN + DLO;
            float p00 = __ldg(&xs0[lane]),      p01 = __ldg(&xs0[lane + 32]);
            float p02 = __ldg(&xs0[lane + 64]), p03 = __ldg(&xs0[lane + 96]);
            float p10 = __ldg(&xs1[lane]),      p11 = __ldg(&xs1[lane + 32]);
            float p12 = __ldg(&xs1[lane + 64]), p13 = __ldg(&xs1[lane + 96]);
            float a0[7], a1[7];
            #pragma unroll
            for (int c = 0; c < 7; c++) {
                a0[c] = __shfl_sync(0xffffffffu, av0, c);
                a1[c] = __shfl_sync(0xffffffffu, av1, c);
            }
            unsigned long long m00 = fadd2(Bp0, pk2(p00, p01));
            unsigned long long m01 = fadd2(Bp1, pk2(p02, p03));
            unsigned long long m10 = fadd2(Bp0, pk2(p10, p11));
            unsigned long long m11 = fadd2(Bp1, pk2(p12, p13));
            #pragma unroll
            for (int c = 0; c < 7; c++) {
                unsigned long long a0p = pk2(a0[c], a0[c]);
                unsigned long long a1p = pk2(a1[c], a1[c]);
                m00 = ffma2(a0p, Wp0[c], m00);
                m01 = ffma2(a0p, Wp1[c], m01);
                m10 = ffma2(a1p, Wp0[c], m10);
                m11 = ffma2(a1p, Wp1[c], m11);
            }
            float u0, u1, u2, u3, v0, v1, v2, v3;
            upk2(m00, u0, u1); upk2(m01, u2, u3);
            upk2(m10, v0, v1); upk2(m11, v2, v3);
            acc0 += fmaxf(u0, 0.f) + fmaxf(v0, 0.f);
            acc1 += fmaxf(u1, 0.f) + fmaxf(v1, 0.f);
            acc2 += fmaxf(u2, 0.f) + fmaxf(v2, 0.f);
            acc3 += fmaxf(u3, 0.f) + fmaxf(v3, 0.f);
            if (REM) {
                float q0 = br, q1 = br;
                if (lane < 3) {
                    q0 += __ldg(&x[(size_t)se0.x * NODE_IN + 384 + lane]);
                    q1 += __ldg(&x[(size_t)se1.x * NODE_IN + 384 + lane]);
                }
                #pragma unroll
                for (int c = 0; c < 7; c++) {
                    q0 = fmaf(a0[c], wr[c], q0);
                    q1 = fmaf(a1[c], wr[c], q1);
                }
                accr += fmaxf(q0, 0.f) + fmaxf(q1, 0.f);
            }
        }
        if (i < end) {
            int2 se0 = g_csr[i];
            float av0 = (lane < 7) ? __ldg(&eattr[(size_t)se0.y * EDGE_DIM + lane]) : 0.f;
            const float* xs0 = x + (size_t)se0.x * NODE_IN + DLO;
            float p00 = __ldg(&xs0[lane]),      p01 = __ldg(&xs0[lane + 32]);
            float p02 = __ldg(&xs0[lane + 64]), p03 = __ldg(&xs0[lane + 96]);
            float a0[7];
            #pragma unroll
            for (int c = 0; c < 7; c++) a0[c] = __shfl_sync(0xffffffffu, av0, c);
            unsigned long long m00 = fadd2(Bp0, pk2(p00, p01));
            unsigned long long m01 = fadd2(Bp1, pk2(p02, p03));
            #pragma unroll
            for (int c = 0; c < 7; c++) {
                unsigned long long a0p = pk2(a0[c], a0[c]);
                m00 = ffma2(a0p, Wp0[c], m00);
                m01 = ffma2(a0p, Wp1[c], m01);
            }
            float u0, u1, u2, u3;
            upk2(m00, u0, u1); upk2(m01, u2, u3);
            acc0 += fmaxf(u0, 0.f);
            acc1 += fmaxf(u1, 0.f);
            acc2 += fmaxf(u2, 0.f);
            acc3 += fmaxf(u3, 0.f);
            if (REM) {
                float q0 = br;
                if (lane < 3) q0 += __ldg(&x[(size_t)se0.x * NODE_IN + 384 + lane]);
                #pragma unroll
                for (int c = 0; c < 7; c++) q0 = fmaf(a0[c], wr[c], q0);
                accr += fmaxf(q0, 0.f);
            }
        }
        float* ar = aggr + (size_t)d * AGGR_LD + DLO;
        ar[lane] = acc0;
        ar[lane + 32] = acc1;
        ar[lane + 64] = acc2;
        ar[lane + 96] = acc3;
        if (REM && lane < 3) aggr[(size_t)d * AGGR_LD + 384 + lane] = accr;
    }
}

// ---------------- conv2: warp-per-dst gather-aggregate, D=128, float4 ----------------
__global__ __launch_bounds__(256) void conv2_pass(
    const float* __restrict__ h, const float* __restrict__ eattr,
    const float* __restrict__ wg, const float* __restrict__ bg,
    float* __restrict__ aggr)
{
    __shared__ __align__(16) float sw[EDGE_DIM * HID];
    __shared__ __align__(16) float sb[HID];
    for (int i = threadIdx.x; i < EDGE_DIM * HID; i += 256) sw[i] = wg[i];
    if (threadIdx.x < HID) sb[threadIdx.x] = bg[threadIdx.x];
    __syncthreads();
    const float4* sw4 = (const float4*)sw;
    const float4* sb4 = (const float4*)sb;

    int lane = threadIdx.x & 31;
    unsigned long long Wlo[7], Whi[7];
    #pragma unroll
    for (int c = 0; c < 7; c++) {
        float4 W = sw4[c * 32 + lane];
        Wlo[c] = pk2(W.x, W.y);
        Whi[c] = pk2(W.z, W.w);
    }
    float4 B = sb4[lane];
    unsigned long long Blo = pk2(B.x, B.y);
    unsigned long long Bhi = pk2(B.z, B.w);

    const float4* h4 = (const float4*)h;
    float4* a4 = (float4*)aggr;

    int gwarp = (blockIdx.x * 256 + threadIdx.x) >> 5;
    int nwarp = (gridDim.x * 256) >> 5;

    for (int d = gwarp; d < N_NODES; d += nwarp) {
        int beg = g_rp[d];
        int end = g_rp[d + 1];
        float4 acc = __ldg(h4 + (size_t)d * 32 + lane);

        int i = beg;
        for (; i + 1 < end; i += 2) {
            int2 se0 = g_csr[i];
            int2 se1 = g_csr[i + 1];
            float av0 = (lane < 7) ? __ldg(&eattr[(size_t)se0.y * EDGE_DIM + lane]) : 0.f;
            float av1 = (lane < 7) ? __ldg(&eattr[(size_t)se1.y * EDGE_DIM + lane]) : 0.f;
            float4 v0 = __ldg(h4 + (size_t)se0.x * 32 + lane);
            float4 v1 = __ldg(h4 + (size_t)se1.x * 32 + lane);
            float a0[7], a1[7];
            #pragma unroll
            for (int c = 0; c < 7; c++) {
                a0[c] = __shfl_sync(0xffffffffu, av0, c);
                a1[c] = __shfl_sync(0xffffffffu, av1, c);
            }
            unsigned long long m0lo = fadd2(Blo, pk2(v0.x, v0.y));
            unsigned long long m0hi = fadd2(Bhi, pk2(v0.z, v0.w));
            unsigned long long m1lo = fadd2(Blo, pk2(v1.x, v1.y));
            unsigned long long m1hi = fadd2(Bhi, pk2(v1.z, v1.w));
            #pragma unroll
            for (int c = 0; c < 7; c++) {
                unsigned long long a0p = pk2(a0[c], a0[c]);
                unsigned long long a1p = pk2(a1[c], a1[c]);
                m0lo = ffma2(a0p, Wlo[c], m0lo);
                m0hi = ffma2(a0p, Whi[c], m0hi);
                m1lo = ffma2(a1p, Wlo[c], m1lo);
                m1hi = ffma2(a1p, Whi[c], m1hi);
            }
            float u0, u1, u2, u3, w0, w1, w2, w3;
            upk2(m0lo, u0, u1); upk2(m0hi, u2, u3);
            upk2(m1lo, w0, w1); upk2(m1hi, w2, w3);
            acc.x += fmaxf(u0, 0.f) + fmaxf(w0, 0.f);
            acc.y += fmaxf(u1, 0.f) + fmaxf(w1, 0.f);
            acc.z += fmaxf(u2, 0.f) + fmaxf(w2, 0.f);
            acc.w += fmaxf(u3, 0.f) + fmaxf(w3, 0.f);
        }
        if (i < end) {
            int2 se0 = g_csr[i];
            float av0 = (lane < 7) ? __ldg(&eattr[(size_t)se0.y * EDGE_DIM + lane]) : 0.f;
            float4 v0 = __ldg(h4 + (size_t)se0.x * 32 + lane);
            float a0[7];
            #pragma unroll
            for (int c = 0; c < 7; c++) a0[c] = __shfl_sync(0xffffffffu, av0, c);
            unsigned long long m0lo = fadd2(Blo, pk2(v0.x, v0.y));
            unsigned long long m0hi = fadd2(Bhi, pk2(v0.z, v0.w));
            #pragma unroll
            for (int c = 0; c < 7; c++) {
                unsigned long long a0p = pk2(a0[c], a0[c]);
                m0lo = ffma2(a0p, Wlo[c], m0lo);
                m0hi = ffma2(a0p, Whi[c], m0hi);
            }
            float u0, u1, u2, u3;
            upk2(m0lo, u0, u1); upk2(m0hi, u2, u3);
            acc.x += fmaxf(u0, 0.f);
            acc.y += fmaxf(u1, 0.f);
            acc.z += fmaxf(u2, 0.f);
            acc.w += fmaxf(u3, 0.f);
        }
        a4[(size_t)d * 32 + lane] = acc;
    }
}

// ---------------- tf32 helpers ----------------
__device__ __forceinline__ uint32_t f2tf32(float f) {
    uint32_t u;
    asm("cvt.rna.tf32.f32 %0, %1;" : "=r"(u) : "f"(f));
    return u;
}

// ---------------- dual tf32 GEMM: gA = A@Wa, gB = A@Wb  (K=128 fixed) ----------------
__global__ __launch_bounds__(256) void gemm_tc2(
    const float* __restrict__ A, const float* __restrict__ W,
    float* __restrict__ C0, float* __restrict__ C1, int M)
{
    __shared__ uint32_t As[128][36];
    __shared__ uint32_t Bs[32][132];

    const float* Wb = W + (size_t)blockIdx.y * 128 * 128;
    float* C = blockIdx.y ? C1 : C0;

    int t = threadIdx.x;
    int lane = t & 31;
    int warp = t >> 5;
    int wm = warp & 3;
    int wn = warp >> 2;
    int row0 = blockIdx.x * 128;
    int g = lane >> 2;
    int tt = lane & 3;

    float c[2][8][4];
    #pragma unroll
    for (int mt = 0; mt < 2; mt++)
        #pragma unroll
        for (int nt = 0; nt < 8; nt++)
            #pragma unroll
            for (int i = 0; i < 4; i++) c[mt][nt][i] = 0.f;

    for (int k0 = 0; k0 < 128; k0 += 32) {
        #pragma unroll
        for (int i = 0; i < 4; i++) {
            int idx = t + i * 256;
            int r = idx >> 3;
            int kq = (idx & 7) * 4;
            int gr = row0 + r;
            float4 v = make_float4(0.f, 0.f, 0.f, 0.f);
            if (gr < M) v = *(const float4*)&A[(size_t)gr * 128 + k0 + kq];
            *(uint4*)&As[r][kq] = make_uint4(f2tf32(v.x), f2tf32(v.y), f2tf32(v.z), f2tf32(v.w));
        }
        #pragma unroll
        for (int i = 0; i < 4; i++) {
            int idx = t + i * 256;
            int kk = idx >> 5;
            int nq = (idx & 31) * 4;
            float4 v = *(const float4*)&Wb[(size_t)(k0 + kk) * 128 + nq];
            *(uint4*)&Bs[kk][nq] = make_uint4(f2tf32(v.x), f2tf32(v.y), f2tf32(v.z), f2tf32(v.w));
        }
        __syncthreads();
        #pragma unroll
        for (int k8 = 0; k8 < 4; k8++) {
            int kb = k8 * 8;
            uint32_t a[2][4], b[8][2];
            #pragma unroll
            for (int mt = 0; mt < 2; mt++) {
                int ar = wm * 32 + mt * 16 + g;
                a[mt][0] = As[ar][kb + tt];
                a[mt][1] = As[ar + 8][kb + tt];
                a[mt][2] = As[ar][kb + tt + 4];
                a[mt][3] = As[ar + 8][kb + tt + 4];
            }
            #pragma unroll
            for (int nt = 0; nt < 8; nt++) {
                int bn = wn * 64 + nt * 8 + g;
                b[nt][0] = Bs[kb + tt][bn];
                b[nt][1] = Bs[kb + tt + 4][bn];
            }
            #pragma unroll
            for (int mt = 0; mt < 2; mt++)
                #pragma unroll
                for (int nt = 0; nt < 8; nt++) {
                    asm volatile(
                        "mma.sync.aligned.m16n8k8.row.col.f32.tf32.tf32.f32 "
                        "{%0,%1,%2,%3}, {%4,%5,%6,%7}, {%8,%9}, {%0,%1,%2,%3};\n"
                        : "+f"(c[mt][nt][0]), "+f"(c[mt][nt][1]),
                          "+f"(c[mt][nt][2]), "+f"(c[mt][nt][3])
                        : "r"(a[mt][0]), "r"(a[mt][1]), "r"(a[mt][2]), "r"(a[mt][3]),
                          "r"(b[nt][0]), "r"(b[nt][1]));
                }
        }
        __syncthreads();
    }

    #pragma unroll
    for (int nt = 0; nt < 8; nt++) {
        int col = wn * 64 + nt * 8 + 2 * tt;
        #pragma unroll
        for (int mt = 0; mt < 2; mt++) {
            int r = row0 + wm * 32 + mt * 16 + g;
            if (r < M)
                *(float2*)&C[(size_t)r * 128 + col] = make_float2(c[mt][nt][0], c[mt][nt][1]);
            if (r + 8 < M)
                *(float2*)&C[(size_t)(r + 8) * 128 + col] = make_float2(c[mt][nt][2], c[mt][nt][3]);
        }
    }
}

// ---------------- fused 2-layer MLP: C = relu(relu(A@W1+b1)@W2+b2), N=128 ----------------
__global__ __launch_bounds__(256) void mlp2_tc(
    const float* __restrict__ A, const float* __restrict__ W1,
    const float* __restrict__ b1, const float* __restrict__ W2,
    const float* __restrict__ b2, float* __restrict__ C,
    int M, int K, int lda)
{
    extern __shared__ uint32_t smemu[];
    uint32_t (*As)[36]  = (uint32_t(*)[36])smemu;
    uint32_t (*Bs)[132] = (uint32_t(*)[132])(smemu + 128 * 36);
    uint32_t (*Mid)[132]= (uint32_t(*)[132])(smemu + 128 * 36 + 32 * 132);

    int t = threadIdx.x;
    int lane = t & 31;
    int warp = t >> 5;
    int wm = warp & 3;
    int wn = warp >> 2;
    int row0 = blockIdx.x * 128;
    int g = lane >> 2;
    int tt = lane & 3;

    float c[2][8][4];
    #pragma unroll
    for (int mt = 0; mt < 2; mt++)
        #pragma unroll
        for (int nt = 0; nt < 8; nt++)
            #pragma unroll
            for (int i = 0; i < 4; i++) c[mt][nt][i] = 0.f;

    for (int k0 = 0; k0 < K; k0 += 32) {
        #pragma unroll
        for (int i = 0; i < 4; i++) {
            int idx = t + i * 256;
            int r = idx >> 3;
            int kq = (idx & 7) * 4;
            int gr = row0 + r;
            int gk = k0 + kq;
            float4 v = make_float4(0.f, 0.f, 0.f, 0.f);
            if (gr < M) {
                if (gk + 3 < K) {
                    v = *(const float4*)&A[(size_t)gr * lda + gk];
                } else {
                    float tv[4] = {0.f, 0.f, 0.f, 0.f};
                    #pragma unroll
                    for (int j = 0; j < 4; j++)
                        if (gk + j < K) tv[j] = __ldg(&A[(size_t)gr * lda + gk + j]);
                    v = make_float4(tv[0], tv[1], tv[2], tv[3]);
                }
            }
            *(uint4*)&As[r][kq] = make_uint4(f2tf32(v.x), f2tf32(v.y), f2tf32(v.z), f2tf32(v.w));
        }
        #pragma unroll
        for (int i = 0; i < 4; i++) {
            int idx = t + i * 256;
            int kk = idx >> 5;
            int nq = (idx & 31) * 4;
            float4 v = make_float4(0.f, 0.f, 0.f, 0.f);
            if (k0 + kk < K) v = *(const float4*)&W1[(size_t)(k0 + kk) * 128 + nq];
            *(uint4*)&Bs[kk][nq] = make_uint4(f2tf32(v.x), f2tf32(v.y), f2tf32(v.z), f2tf32(v.w));
        }
        __syncthreads();
        #pragma unroll
        for (int k8 = 0; k8 < 4; k8++) {
            int kb = k8 * 8;
            uint32_t a[2][4], b[8][2];
            #pragma unroll
            for (int mt = 0; mt < 2; mt++) {
                int ar = wm * 32 + mt * 16 + g;
                a[mt][0] = As[ar][kb + tt];
                a[mt][1] = As[ar + 8][kb + tt];
                a[mt][2] = As[ar][kb + tt + 4];
                a[mt][3] = As[ar + 8][kb + tt + 4];
            }
            #pragma unroll
            for (int nt = 0; nt < 8; nt++) {
                int bn = wn * 64 + nt * 8 + g;
                b[nt][0] = Bs[kb + tt][bn];
                b[nt][1] = Bs[kb + tt + 4][bn];
            }
            #pragma unroll
            for (int mt = 0; mt < 2; mt++)
                #pragma unroll
                for (int nt = 0; nt < 8; nt++) {
                    asm volatile(
                        "mma.sync.aligned.m16n8k8.row.col.f32.tf32.tf32.f32 "
                        "{%0,%1,%2,%3}, {%4,%5,%6,%7}, {%8,%9}, {%0,%1,%2,%3};\n"
                        : "+f"(c[mt][nt][0]), "+f"(c[mt][nt][1]),
                          "+f"(c[mt][nt][2]), "+f"(c[mt][nt][3])
                        : "r"(a[mt][0]), "r"(a[mt][1]), "r"(a[mt][2]), "r"(a[mt][3]),
                          "r"(b[nt][0]), "r"(b[nt][1]));
                }
        }
        __syncthreads();
    }

    #pragma unroll
    for (int nt = 0; nt < 8; nt++) {
        int col = wn * 64 + nt * 8 + 2 * tt;
        float bb0 = __ldg(&b1[col]);
        float bb1 = __ldg(&b1[col + 1]);
        #pragma unroll
        for (int mt = 0; mt < 2; mt++) {
            int r = wm * 32 + mt * 16 + g;
            Mid[r][col]         = f2tf32(fmaxf(c[mt][nt][0] + bb0, 0.f));
            Mid[r][col + 1]     = f2tf32(fmaxf(c[mt][nt][1] + bb1, 0.f));
            Mid[r + 8][col]     = f2tf32(fmaxf(c[mt][nt][2] + bb0, 0.f));
            Mid[r + 8][col + 1] = f2tf32(fmaxf(c[mt][nt][3] + bb1, 0.f));
            c[mt][nt][0] = 0.f; c[mt][nt][1] = 0.f; c[mt][nt][2] = 0.f; c[mt][nt][3] = 0.f;
        }
    }
    __syncthreads();

    for (int k0 = 0; k0 < 128; k0 += 32) {
        #pragma unroll
        for (int i = 0; i < 4; i++) {
            int idx = t + i * 256;
            int kk = idx >> 5;
            int nq = (idx & 31) * 4;
            float4 v = *(const float4*)&W2[(size_t)(k0 + kk) * 128 + nq];
            *(uint4*)&Bs[kk][nq] = make_uint4(f2tf32(v.x), f2tf32(v.y), f2tf32(v.z), f2tf32(v.w));
        }
        __syncthreads();
        #pragma unroll
        for (int k8 = 0; k8 < 4; k8++) {
            int kb = k0 + k8 * 8;
            uint32_t a[2][4], b[8][2];
            #pragma unroll
            for (int mt = 0; mt < 2; mt++) {
                int ar = wm * 32 + mt * 16 + g;
                a[mt][0] = Mid[ar][kb + tt];
                a[mt][1] = Mid[ar + 8][kb + tt];
                a[mt][2] = Mid[ar][kb + tt + 4];
                a[mt][3] = Mid[ar + 8][kb + tt + 4];
            }
            #pragma unroll
            for (int nt = 0; nt < 8; nt++) {
                int bn = wn * 64 + nt * 8 + g;
                b[nt][0] = Bs[(k8 * 8) + tt][bn];
                b[nt][1] = Bs[(k8 * 8) + tt + 4][bn];
            }
            #pragma unroll
            for (int mt = 0; mt < 2; mt++)
                #pragma unroll
                for (int nt = 0; nt < 8; nt++) {
                    asm volatile(
                        "mma.sync.aligned.m16n8k8.row.col.f32.tf32.tf32.f32 "
                        "{%0,%1,%2,%3}, {%4,%5,%6,%7}, {%8,%9}, {%0,%1,%2,%3};\n"
                        : "+f"(c[mt][nt][0]), "+f"(c[mt][nt][1]),
                          "+f"(c[mt][nt][2]), "+f"(c[mt][nt][3])
                        : "r"(a[mt][0]), "r"(a[mt][1]), "r"(a[mt][2]), "r"(a[mt][3]),
                          "r"(b[nt][0]), "r"(b[nt][1]));
                }
        }
        __syncthreads();
    }

    #pragma unroll
    for (int nt = 0; nt < 8; nt++) {
        int col = wn * 64 + nt * 8 + 2 * tt;
        float bb0 = __ldg(&b2[col]);
        float bb1 = __ldg(&b2[col + 1]);
        #pragma unroll
        for (int mt = 0; mt < 2; mt++) {
            int r = row0 + wm * 32 + mt * 16 + g;
            float v0 = fmaxf(c[mt][nt][0] + bb0, 0.f);
            float v1 = fmaxf(c[mt][nt][1] + bb1, 0.f);
            float v2 = fmaxf(c[mt][nt][2] + bb0, 0.f);
            float v3 = fmaxf(c[mt][nt][3] + bb1, 0.f);
            if (r < M)     *(float2*)&C[(size_t)r * 128 + col]       = make_float2(v0, v1);
            if (r + 8 < M) *(float2*)&C[(size_t)(r + 8) * 128 + col] = make_float2(v2, v3);
        }
    }
}

// ---------------- decomposed edge MLP output stage ----------------
__global__ __launch_bounds__(512) void edge_out(
    const float* __restrict__ Arow, const float* __restrict__ Brow,
    const float* __restrict__ eattr,
    const float* __restrict__ w1g,
    const float* __restrict__ b1g,
    const float* __restrict__ w2g, const float* __restrict__ b2g,
    float* __restrict__ out)
{
    __shared__ __align__(16) float wc[EDGE_DIM * 128];
    __shared__ __align__(16) float b1s[128];
    __shared__ float w2s[256];
    __shared__ float b2s[2];

    int t = threadIdx.x;
    for (int i = t; i < EDGE_DIM * 128; i += 512) wc[i] = w1g[256 * 128 + i];
    if (t < 128) b1s[t] = b1g[t];
    if (t < 256) w2s[t] = w2g[t];
    if (t < 2)   b2s[t] = b2g[t];
    __syncthreads();

    int lane = t & 31;
    int w = t >> 5;
    int gw = blockIdx.x * 16 + w;
    int ngw = gridDim.x * 16;

    const float4* A4 = (const float4*)Arow;
    const float4* B4 = (const float4*)Brow;
    const float4* wc4 = (const float4*)wc;

    float4 bb = *(const float4*)&b1s[lane * 4];
    float w20 = w2s[(lane * 4 + 0) * 2 + 0], w21 = w2s[(lane * 4 + 0) * 2 + 1];
    float w22 = w2s[(lane * 4 + 1) * 2 + 0], w23 = w2s[(lane * 4 + 1) * 2 + 1];
    float w24 = w2s[(lane * 4 + 2) * 2 + 0], w25 = w2s[(lane * 4 + 2) * 2 + 1];
    float w26 = w2s[(lane * 4 + 3) * 2 + 0], w27 = w2s[(lane * 4 + 3) * 2 + 1];
    float bo0 = b2s[0], bo1 = b2s[1];

    for (int p = gw; p < N_EDGES / 2; p += ngw) {
        int e0 = 2 * p, e1 = e0 + 1;
        int2 ss = *(const int2*)&g_src[e0];
        int2 dd = *(const int2*)&g_dst[e0];
        float4 va0 = A4[(size_t)ss.x * 32 + lane];
        float4 vb0 = B4[(size_t)dd.x * 32 + lane];
        float4 va1 = A4[(size_t)ss.y * 32 + lane];
        float4 vb1 = B4[(size_t)dd.y * 32 + lane];

        float av = (lane < 14) ? eattr[(size_t)e0 * EDGE_DIM + lane] : 0.f;
        float a0[7], a1[7];
        #pragma unroll
        for (int c = 0; c < 7; c++) {
            a0[c] = __shfl_sync(0xffffffffu, av, c);
            a1[c] = __shfl_sync(0xffffffffu, av, c + 7);
        }

        float4 c0 = make_float4(0.f, 0.f, 0.f, 0.f);
        float4 c1 = make_float4(0.f, 0.f, 0.f, 0.f);
        #pragma unroll
        for (int k = 0; k < EDGE_DIM; k++) {
            float4 wv = wc4[k * 32 + lane];
            c0.x = fmaf(a0[k], wv.x, c0.x); c1.x = fmaf(a1[k], wv.x, c1.x);
            c0.y = fmaf(a0[k], wv.y, c0.y); c1.y = fmaf(a1[k], wv.y, c1.y);
            c0.z = fmaf(a0[k], wv.z, c0.z); c1.z = fmaf(a1[k], wv.z, c1.z);
            c0.w = fmaf(a0[k], wv.w, c0.w); c1.w = fmaf(a1[k], wv.w, c1.w);
        }

        float h00 = fmaxf(va0.x + vb0.x + c0.x + bb.x, 0.f);
        float h01 = fmaxf(va0.y + vb0.y + c0.y + bb.y, 0.f);
        float h02 = fmaxf(va0.z + vb0.z + c0.z + bb.z, 0.f);
        float h03 = fmaxf(va0.w + vb0.w + c0.w + bb.w, 0.f);
        float h10 = fmaxf(va1.x + vb1.x + c1.x + bb.x, 0.f);
        float h11 = fmaxf(va1.y + vb1.y + c1.y + bb.y, 0.f);
        float h12 = fmaxf(va1.z + vb1.z + c1.z + bb.z, 0.f);
        float h13 = fmaxf(va1.w + vb1.w + c1.w + bb.w, 0.f);

        float s0o = h00 * w20 + h01 * w22 + h02 * w24 + h03 * w26;
        float s1o = h00 * w21 + h01 * w23 + h02 * w25 + h03 * w27;
        float s2o = h10 * w20 + h11 * w22 + h12 * w24 + h13 * w26;
        float s3o = h10 * w21 + h11 * w23 + h12 * w25 + h13 * w27;

        #pragma unroll
        for (int off = 16; off; off >>= 1) {
            s0o += __shfl_down_sync(0xffffffffu, s0o, off);
            s1o += __shfl_down_sync(0xffffffffu, s1o, off);
            s2o += __shfl_down_sync(0xffffffffu, s2o, off);
            s3o += __shfl_down_sync(0xffffffffu, s3o, off);
        }
        if (lane == 0) {
            *(float2*)&out[(size_t)e0 * 2] = make_float2(s0o + bo0, s1o + bo1);
            *(float2*)&out[(size_t)e1 * 2] = make_float2(s2o + bo0, s3o + bo1);
        }
    }
}

// ---------------- launch ----------------
extern "C" void kernel_launch(void* const* d_in, const int* in_sizes, int n_in,
                              void* d_out, int out_size) {
    const float* x    = (const float*)d_in[0];
    const void*  ei   = d_in[1];
    const float* ea   = (const float*)d_in[2];
    const float* e1w  = (const float*)d_in[3];
    const float* e1b  = (const float*)d_in[4];
    const float* m1w1 = (const float*)d_in[5];
    const float* m1b1 = (const float*)d_in[6];
    const float* m1w2 = (const float*)d_in[7];
    const float* m1b2 = (const float*)d_in[8];
    const float* e2w  = (const float*)d_in[9];
    const float* e2b  = (const float*)d_in[10];
    const float* m2w1 = (const float*)d_in[11];
    const float* m2b1 = (const float*)d_in[12];
    const float* m2w2 = (const float*)d_in[13];
    const float* m2b2 = (const float*)d_in[14];
    const float* emw1 = (const float*)d_in[15];
    const float* emb1 = (const float*)d_in[16];
    const float* emw2 = (const float*)d_in[17];
    const float* emb2 = (const float*)d_in[18];
    float* out = (float*)d_out;

    float *aggr1, *h1, *aggr2, *h2;
    cudaGetSymbolAddress((void**)&aggr1, g_aggr1);
    cudaGetSymbolAddress((void**)&h1,    g_h1);
    cudaGetSymbolAddress((void**)&aggr2, g_aggr2);
    cudaGetSymbolAddress((void**)&h2,    g_h2);
    float* gA = aggr1;                                  // reuse aggr1 after conv1
    float* gB = aggr1 + (size_t)N_NODES * HID;

    size_t mlp_smem = (size_t)(128 * 36 + 32 * 132 + 128 * 132) * 4;
    cudaFuncSetAttribute(mlp2_tc, cudaFuncAttributeMaxDynamicSharedMemorySize, (int)mlp_smem);

    int gemm_grid = (N_NODES + 127) / 128;

    // CSR build: zero + convert/hist + scan(3) + fill
    zero_cnt<<<NP1, 1024>>>();
    convert_hist<<<1024, 256>>>(ei);
    scan1<<<NP1, 1024>>>();
    scan2<<<1, 128>>>();
    scan3<<<NP1, 1024>>>();
    fill_csr<<<1024, 256>>>();

    // conv1: 3 L2-blocked warp-per-dst gather passes (no atomics, no init)
    conv1_pass<0,   false><<<2048, 256>>>(x, ea, e1w, e1b, aggr1);
    conv1_pass<128, false><<<2048, 256>>>(x, ea, e1w, e1b, aggr1);
    conv1_pass<256, true ><<<2048, 256>>>(x, ea, e1w, e1b, aggr1);
    mlp2_tc<<<gemm_grid, 256, mlp_smem>>>(aggr1, m1w1, m1b1, m1w2, m1b2, h1,
                                          N_NODES, NODE_IN, AGGR_LD);

    // conv2: warp-per-dst gather (seeds h1 inline; no copy4)
    conv2_pass<<<2048, 256>>>(h1, ea, e2w, e2b, aggr2);
    mlp2_tc<<<gemm_grid, 256, mlp_smem>>>(aggr2, m2w1, m2b1, m2w2, m2b2, h2,
                                          N_NODES, HID, HID);

    // edge MLP (decomposed): gA = h2@Wa, gB = h2@Wb in one launch
    {
        dim3 grid(gemm_grid, 2);
        gemm_tc2<<<grid, 256>>>(h2, emw1, gA, gB, N_NODES);
    }
    edge_out<<<296, 512>>>(gA, gB, ea, emw1, emb1, emw2, emb2, out);
}